// round 16
// baseline (speedup 1.0000x reference)
#include <cuda_runtime.h>
#include <cuda_fp16.h>
#include <cstdint>

// ---------------- problem constants ----------------
#define NS      1024
#define NV      99
#define ROWS    (NS*NV)       // 101376
#define INCH    64
#define MH      512
#define SH      512
#define KCAT    (INCH+MH)     // 576
#define SCALE0  30.0f

// ---------------- device scratch ----------------
__device__ __half g_hW1[SH*SH];
__device__ __half g_hW2[SH*SH];
__device__ float  g_wdec[3*SH];
__device__ __half g_s0h[NV*SH];              // half(s0)
__device__ __half g_gc0[NS*MH];              // half(1 - M0)
__device__ __half g_gc1[NS*MH];              // half(1 - M1)
__device__ float  g_M2[NS*MH];
__device__ float  g_Z0[NS*KCAT];
__device__ float  g_Z1[NS*KCAT];
__device__ __half g_hHB[(size_t)ROWS*SH];    // ungated sin(S1)
__device__ float  g_dir8[(size_t)ROWS*24];   // 8 partials x 3 dims per row

__device__ __forceinline__ float rna_tf32(float x){
    float y; asm("cvt.rna.tf32.f32 %0, %1;" : "=f"(y) : "f"(x)); return y;
}
__device__ __forceinline__ void cp16(uint32_t s, const void* g){
    asm volatile("cp.async.cg.shared.global [%0], [%1], 16;" :: "r"(s), "l"(g));
}
__device__ __forceinline__ void ldsm4(uint32_t& r0, uint32_t& r1, uint32_t& r2, uint32_t& r3,
                                      uint32_t addr){
    asm volatile("ldmatrix.sync.aligned.m8n8.x4.shared.b16 {%0,%1,%2,%3}, [%4];"
                 : "=r"(r0), "=r"(r1), "=r"(r2), "=r"(r3) : "r"(addr));
}

// ---------------- shared rownorm body ----------------
__device__ __forceinline__ void rownorm_row(const float* __restrict__ v,
                                            const float* __restrict__ g,
                                            float* o32, __half* o16,
                                            int cols, int r, int mode, int tid,
                                            float* red)
{
    const float* vr = v + (size_t)r * cols;
    float ss = 0.f;
    for (int c = tid; c < cols; c += 256) { float x = vr[c]; ss += x * x; }
    red[tid] = ss; __syncthreads();
    for (int s = 128; s > 0; s >>= 1) {
        if (tid < s) red[tid] += red[tid + s];
        __syncthreads();
    }
    float scale = g[r] * rsqrtf(red[0]);
    for (int c = tid; c < cols; c += 256) {
        float w = vr[c] * scale;
        if (mode == 2)      o16[(size_t)r * cols + c] = __float2half(w);
        else                o32[(size_t)r * cols + c] = w;
    }
}

// ================= zfill: Z prefix = rna(X) =================
__global__ void zfill_kernel(const float* __restrict__ X)
{
    int i = blockIdx.x * 256 + threadIdx.x;    // 0..65535
    float v = rna_tf32(X[i]);
    int s = i >> 6, c = i & 63;
    g_Z0[(size_t)s * KCAT + c] = v;
    g_Z1[(size_t)s * KCAT + c] = v;
}

// ================= prep_rest: siren weight-norms + s0 table =====================
__global__ void prep_rest_kernel(const float* __restrict__ sv1, const float* __restrict__ sg1,
                                 const float* __restrict__ sv2, const float* __restrict__ sg2,
                                 const float* __restrict__ dv,  const float* __restrict__ dg,
                                 const float* __restrict__ sv0, const float* __restrict__ sg0,
                                 const float* __restrict__ sb0)
{
    __shared__ float red[256];
    int b = blockIdx.x, tid = threadIdx.x;
    if (b < 1025) {
        if      (b < 512)  rownorm_row(sv1, sg1, nullptr, g_hW1, SH, b,       2, tid, red);
        else if (b < 1024) rownorm_row(sv2, sg2, nullptr, g_hW2, SH, b - 512, 2, tid, red);
        else {
            for (int r = 0; r < 3; r++) rownorm_row(dv, dg, g_wdec, nullptr, SH, r, 0, tid, red);
        }
    } else {                            // s0 table (half): 99 blocks
        int p = b - 1025;
        float t = (float)p / 99.f;
        for (int j = tid; j < SH; j += 256) {
            float vv = sv0[j];
            float w  = sg0[j] * vv * rsqrtf(vv * vv);
            g_s0h[p * SH + j] = __float2half(sinf(SCALE0 * (t * w + sb0[j])));
        }
    }
}

// ================= mod GEMM: raw weights, fused weight-norm in epilogue ==========
// out(optional fp32) = silu(scale*acc+bias); hcout(optional) = half(1 - silu(...))
#define BMM 64
#define BNM 64
#define BKM 32
#define SST 36
#define MOD_STAGES 4
__global__ __launch_bounds__(256, 2)
void gemm_mod_kernel(const float* __restrict__ A, const float* __restrict__ V,
                     const float* __restrict__ gvec, const float* __restrict__ bias,
                     float* __restrict__ out, float* __restrict__ zout,
                     __half* __restrict__ hcout, int K)
{
    extern __shared__ float sm[];
    float* sA = sm;
    float* sB = sm + MOD_STAGES * BMM * SST;
    const int tid = threadIdx.x;
    const int rowBase = blockIdx.y * BMM;
    const int colBase = blockIdx.x * BNM;
    const uint32_t sA_u = (uint32_t)__cvta_generic_to_shared(sA);
    const uint32_t sB_u = (uint32_t)__cvta_generic_to_shared(sB);
    const int lane = tid & 31, warp = tid >> 5;
    const int wm = warp & 3, wn = warp >> 2;         // warp tile 16 x 32
    const int gg = lane >> 2, tt = lane & 3;
    float acc[4][4] = {};
    float ss[4] = {0.f, 0.f, 0.f, 0.f};
    const int nk = K / BKM;

    auto load_stage = [&](int i, int buf){
        int k0 = i * BKM;
        #pragma unroll
        for (int it = 0; it < 2; it++){
            int c  = tid + it * 256;
            int r  = c >> 3;
            int kc = (c & 7) * 4;
            cp16(sA_u + (uint32_t)((buf * BMM * SST + r * SST + kc) * 4),
                 &A[(size_t)(rowBase + r) * K + k0 + kc]);
            cp16(sB_u + (uint32_t)((buf * BNM * SST + r * SST + kc) * 4),
                 &V[(size_t)(colBase + r) * K + k0 + kc]);
        }
        asm volatile("cp.async.commit_group;");
    };

    for (int s = 0; s < (nk < 3 ? nk : 3); s++) load_stage(s, s);

    for (int i = 0; i < nk; i++){
        if      (i + 3 <= nk) asm volatile("cp.async.wait_group 2;" ::: "memory");
        else if (i + 2 <= nk) asm volatile("cp.async.wait_group 1;" ::: "memory");
        else                  asm volatile("cp.async.wait_group 0;" ::: "memory");
        __syncthreads();
        const float* cA = sA + (i % MOD_STAGES) * BMM * SST;
        const float* cB = sB + (i % MOD_STAGES) * BNM * SST;
        #pragma unroll
        for (int kk = 0; kk < BKM; kk += 8){
            uint32_t a[4], b[4][2];
            {
                int r = wm * 16 + gg;
                a[0] = __float_as_uint(rna_tf32(cA[r * SST + kk + tt]));
                a[1] = __float_as_uint(rna_tf32(cA[(r + 8) * SST + kk + tt]));
                a[2] = __float_as_uint(rna_tf32(cA[r * SST + kk + tt + 4]));
                a[3] = __float_as_uint(rna_tf32(cA[(r + 8) * SST + kk + tt + 4]));
            }
            #pragma unroll
            for (int ni = 0; ni < 4; ni++){
                int c = wn * 32 + ni * 8 + gg;
                float bf0 = cB[c * SST + kk + tt];
                float bf1 = cB[c * SST + kk + tt + 4];
                ss[ni] = fmaf(bf0, bf0, ss[ni]);
                ss[ni] = fmaf(bf1, bf1, ss[ni]);
                b[ni][0] = __float_as_uint(rna_tf32(bf0));
                b[ni][1] = __float_as_uint(rna_tf32(bf1));
            }
            #pragma unroll
            for (int ni = 0; ni < 4; ni++){
                float* d = acc[ni];
                asm volatile(
                    "mma.sync.aligned.m16n8k8.row.col.f32.tf32.tf32.f32 "
                    "{%0,%1,%2,%3}, {%4,%5,%6,%7}, {%8,%9}, {%0,%1,%2,%3};"
                    : "+f"(d[0]), "+f"(d[1]), "+f"(d[2]), "+f"(d[3])
                    : "r"(a[0]), "r"(a[1]), "r"(a[2]), "r"(a[3]),
                      "r"(b[ni][0]), "r"(b[ni][1]));
            }
        }
        __syncthreads();
        if (i + 3 < nk) load_stage(i + 3, (i + 3) % MOD_STAGES);
    }

    // sumsq quad reduce: all 4 lanes of each quad hold the col (ni*8+gg) total
    #pragma unroll
    for (int ni = 0; ni < 4; ni++){
        ss[ni] += __shfl_xor_sync(0xFFFFFFFFu, ss[ni], 1);
        ss[ni] += __shfl_xor_sync(0xFFFFFFFFu, ss[ni], 2);
    }

    int row0 = rowBase + wm * 16 + gg;
    #pragma unroll
    for (int ni = 0; ni < 4; ni++){
        int col = colBase + wn * 32 + ni * 8 + tt * 2;
        float s0 = __shfl_sync(0xFFFFFFFFu, ss[ni], tt * 8);        // gg = 2tt quad
        float s1 = __shfl_sync(0xFFFFFFFFu, ss[ni], tt * 8 + 4);    // gg = 2tt+1 quad
        float sc0 = gvec[col]     * rsqrtf(s0);
        float sc1 = gvec[col + 1] * rsqrtf(s1);
        float b0 = bias[col], b1 = bias[col + 1];
        #pragma unroll
        for (int h = 0; h < 2; h++){
            int row = row0 + h * 8;
            float v0 = acc[ni][h * 2 + 0] * sc0 + b0;
            float v1 = acc[ni][h * 2 + 1] * sc1 + b1;
            v0 = v0 / (1.f + __expf(-v0));
            v1 = v1 / (1.f + __expf(-v1));
            if (out)
                *reinterpret_cast<float2*>(&out[(size_t)row * 512 + col]) = make_float2(v0, v1);
            if (hcout)
                *reinterpret_cast<__half2*>(&hcout[(size_t)row * 512 + col]) =
                    __floats2half2_rn(1.f - v0, 1.f - v1);
            if (zout)
                *reinterpret_cast<float2*>(&zout[(size_t)row * KCAT + 64 + col]) =
                    make_float2(rna_tf32(v0), rna_tf32(v1));
        }
    }
}

// ================= fp16 tensor-core GEMM (rows-chunked), 3-stage pipeline ========
// MODE 1: A = gc0(half)*s0h(half) on the fly; epilogue stores half sin(acc+b) UNGATED.
// MODE 2: A = hHB(half)*gc1(half) on the fly; epilogue gates by (1-M2), decoder
//         partials -> g_dir8 (per-warp slot, race-free).
#define BK2 64
#define TC_STAGES 3

template<int MODE>
__global__ __launch_bounds__(256, 2)
void tc_fp16_kernel(const __half* __restrict__ A, const __half* __restrict__ W,
                    const float* __restrict__ bias, const float* __restrict__ gateE,
                    const __half* __restrict__ gateA, __half* __restrict__ out, int rowOff)
{
    extern __shared__ __align__(1024) char smem_raw[];
    uint32_t base  = (uint32_t)__cvta_generic_to_shared(smem_raw);
    uint32_t abase = (base + 1023u) & ~1023u;
    const int tid = threadIdx.x, warp = tid >> 5, lane = tid & 31;
    const int rowBase = rowOff + blockIdx.y * 128, colBase = blockIdx.x * 128;
    const int wm = warp & 3, wn = warp >> 2;
    const int gl = (lane >> 3) & 1, gh = lane >> 4, lr = lane & 7;

    float* wds = reinterpret_cast<float*>(smem_raw + (abase - base) + TC_STAGES * 32768);
    if (MODE == 2 && tid < 128) {
        #pragma unroll
        for (int d = 0; d < 3; d++)
            wds[d * 128 + tid] = g_wdec[d * 512 + colBase + tid];
    }

    auto load_B = [&](int t, int buf){
        uint32_t bBuf = abase + buf * 32768 + 16384;
        int k0 = t * BK2;
        #pragma unroll
        for (int it = 0; it < 4; it++){
            int idx = tid + it * 256;
            int r = idx >> 3, c = idx & 7;
            uint32_t off = (uint32_t)(r * 128 + ((c ^ (r & 7)) * 16));
            cp16(bBuf + off, &W[(size_t)(colBase + r) * 512 + k0 + c * 8]);
        }
    };
    // MODE 1: gc0[strand] * s0h[point];  MODE 2: A[row] * gc1[strand]
    auto produce_A = [&](int t, int buf){
        uint32_t aBuf = abase + buf * 32768;
        int k0 = t * BK2;
        #pragma unroll
        for (int it = 0; it < 4; it++){
            int idx = tid + it * 256;
            int r = idx >> 3, c = idx & 7;
            int row = rowBase + r;
            int strand = row / NV, p = row - strand * NV;
            uint4 mv = *reinterpret_cast<const uint4*>(&gateA[(size_t)strand * MH + k0 + c * 8]);
            uint4 sv;
            if (MODE == 1)
                sv = *reinterpret_cast<const uint4*>(&g_s0h[p * SH + k0 + c * 8]);
            else
                sv = *reinterpret_cast<const uint4*>(&A[(size_t)row * 512 + k0 + c * 8]);
            __half2 h0 = __hmul2(*reinterpret_cast<__half2*>(&mv.x), *reinterpret_cast<__half2*>(&sv.x));
            __half2 h1 = __hmul2(*reinterpret_cast<__half2*>(&mv.y), *reinterpret_cast<__half2*>(&sv.y));
            __half2 h2 = __hmul2(*reinterpret_cast<__half2*>(&mv.z), *reinterpret_cast<__half2*>(&sv.z));
            __half2 h3 = __hmul2(*reinterpret_cast<__half2*>(&mv.w), *reinterpret_cast<__half2*>(&sv.w));
            uint32_t off = (uint32_t)(r * 128 + ((c ^ (r & 7)) * 16));
            asm volatile("st.shared.v4.b32 [%0], {%1,%2,%3,%4};"
                         :: "r"(aBuf + off),
                            "r"(*reinterpret_cast<uint32_t*>(&h0)),
                            "r"(*reinterpret_cast<uint32_t*>(&h1)),
                            "r"(*reinterpret_cast<uint32_t*>(&h2)),
                            "r"(*reinterpret_cast<uint32_t*>(&h3)) : "memory");
        }
    };
    auto load_stage = [&](int t, int buf){
        produce_A(t, buf);
        load_B(t, buf);
        asm volatile("cp.async.commit_group;");
    };

    float acc[2][8][4] = {};

    load_stage(0, 0);
    load_stage(1, 1);
    load_stage(2, 2);

    for (int t = 0; t < 8; t++){
        if (t < 7) asm volatile("cp.async.wait_group 2;" ::: "memory");
        else       asm volatile("cp.async.wait_group 0;" ::: "memory");
        __syncthreads();
        int buf = t % TC_STAGES;
        uint32_t aBuf = abase + buf * 32768;
        uint32_t bBuf = aBuf + 16384;

        #pragma unroll
        for (int kk = 0; kk < 4; kk++){
            int kc = kk * 2 + gh;
            uint32_t a[2][4], b[4][4];
            #pragma unroll
            for (int mi = 0; mi < 2; mi++){
                int row = wm * 32 + mi * 16 + gl * 8 + lr;
                ldsm4(a[mi][0], a[mi][1], a[mi][2], a[mi][3],
                      aBuf + (uint32_t)(row * 128 + ((kc ^ lr) * 16)));
            }
            #pragma unroll
            for (int nq = 0; nq < 4; nq++){
                int nrow = wn * 64 + nq * 16 + gl * 8 + lr;
                ldsm4(b[nq][0], b[nq][1], b[nq][2], b[nq][3],
                      bBuf + (uint32_t)(nrow * 128 + ((kc ^ lr) * 16)));
            }
            #pragma unroll
            for (int mi = 0; mi < 2; mi++)
                #pragma unroll
                for (int nq = 0; nq < 4; nq++){
                    #pragma unroll
                    for (int hf = 0; hf < 2; hf++){
                        float* d = acc[mi][nq * 2 + hf];
                        asm volatile(
                            "mma.sync.aligned.m16n8k16.row.col.f32.f16.f16.f32 "
                            "{%0,%1,%2,%3}, {%4,%5,%6,%7}, {%8,%9}, {%0,%1,%2,%3};"
                            : "+f"(d[0]), "+f"(d[1]), "+f"(d[2]), "+f"(d[3])
                            : "r"(a[mi][0]), "r"(a[mi][1]), "r"(a[mi][2]), "r"(a[mi][3]),
                              "r"(b[nq][hf]), "r"(b[nq][2 + hf]));
                    }
                }
        }
        __syncthreads();
        if (t + 3 < 8) load_stage(t + 3, (t + 3) % TC_STAGES);
    }

    // ---- epilogue ----
    const int gg = lane >> 2, tt = lane & 3;
    float p3[4][3];
    if (MODE == 2){
        #pragma unroll
        for (int q = 0; q < 4; q++){ p3[q][0] = 0.f; p3[q][1] = 0.f; p3[q][2] = 0.f; }
    }
    #pragma unroll
    for (int mi = 0; mi < 2; mi++){
        int row0 = rowBase + wm * 32 + mi * 16 + gg;
        #pragma unroll
        for (int ni = 0; ni < 8; ni++){
            int col = colBase + wn * 64 + ni * 8 + tt * 2;
            float b0 = bias[col], b1 = bias[col + 1];
            #pragma unroll
            for (int h = 0; h < 2; h++){
                int row = row0 + h * 8;
                if (MODE == 1){
                    float v0 = __sinf(acc[mi][ni][h * 2 + 0] + b0);
                    float v1 = __sinf(acc[mi][ni][h * 2 + 1] + b1);
                    *reinterpret_cast<__half2*>(&out[(size_t)row * 512 + col]) =
                        __floats2half2_rn(v0, v1);
                } else {
                    int strand = row / NV;
                    float g0 = 1.f - gateE[(size_t)strand * MH + col];
                    float g1 = 1.f - gateE[(size_t)strand * MH + col + 1];
                    float v0 = g0 * __sinf(acc[mi][ni][h * 2 + 0] + b0);
                    float v1 = g1 * __sinf(acc[mi][ni][h * 2 + 1] + b1);
                    int lc = col - colBase;
                    int q = mi * 2 + h;
                    #pragma unroll
                    for (int d = 0; d < 3; d++)
                        p3[q][d] += v0 * wds[d * 128 + lc] + v1 * wds[d * 128 + lc + 1];
                }
            }
        }
    }
    if (MODE == 2){
        #pragma unroll
        for (int q = 0; q < 4; q++)
            #pragma unroll
            for (int d = 0; d < 3; d++){
                float v = p3[q][d];
                v += __shfl_xor_sync(0xFFFFFFFFu, v, 1);
                v += __shfl_xor_sync(0xFFFFFFFFu, v, 2);
                p3[q][d] = v;
            }
        if (tt == 0){
            int slot = blockIdx.x * 2 + wn;     // 8 race-free slots per row
            int rb = rowBase + wm * 32 + gg;
            #pragma unroll
            for (int q = 0; q < 4; q++){
                int row = rb + (q & 1) * 8 + (q >> 1) * 16;
                #pragma unroll
                for (int d = 0; d < 3; d++)
                    g_dir8[(size_t)row * 24 + slot * 3 + d] = p3[q][d] * 0.01f;
            }
        }
    }
}

// ================= cumsum: warp per strand, shfl inclusive scan =================
__global__ void cumsum_kernel(float* __restrict__ out, const float* __restrict__ bd)
{
    int gw = (blockIdx.x * blockDim.x + threadIdx.x) >> 5;   // strand
    int lane = threadIdx.x & 31;
    if (gw >= NS) return;
    int s = gw;
    float bias0 = bd[0] * 0.01f, bias1 = bd[1] * 0.01f, bias2 = bd[2] * 0.01f;
    if (lane < 3) out[(size_t)s * 300 + lane] = 0.f;
    float c0 = 0.f, c1 = 0.f, c2 = 0.f;
    #pragma unroll
    for (int ch = 0; ch < 4; ch++){
        int p = ch * 32 + lane;
        float v0 = 0.f, v1 = 0.f, v2 = 0.f;
        if (p < NV){
            const float* b = &g_dir8[(size_t)(s * NV + p) * 24];
            #pragma unroll
            for (int j = 0; j < 8; j++){
                v0 += b[j * 3 + 0];
                v1 += b[j * 3 + 1];
                v2 += b[j * 3 + 2];
            }
            v0 += bias0; v1 += bias1; v2 += bias2;
        }
        #pragma unroll
        for (int o = 1; o < 32; o <<= 1){
            float t0 = __shfl_up_sync(0xFFFFFFFFu, v0, o);
            float t1 = __shfl_up_sync(0xFFFFFFFFu, v1, o);
            float t2 = __shfl_up_sync(0xFFFFFFFFu, v2, o);
            if (lane >= o){ v0 += t0; v1 += t1; v2 += t2; }
        }
        v0 += c0; v1 += c1; v2 += c2;
        if (p < NV){
            float* ob = out + (size_t)s * 300 + (size_t)(p + 1) * 3;
            ob[0] = v0; ob[1] = v1; ob[2] = v2;
        }
        c0 = __shfl_sync(0xFFFFFFFFu, v0, 31);
        c1 = __shfl_sync(0xFFFFFFFFu, v1, 31);
        c2 = __shfl_sync(0xFFFFFFFFu, v2, 31);
    }
}

// ================= host launch =================
static void* sym(const void* s) { void* p = nullptr; cudaGetSymbolAddress(&p, s); return p; }

extern "C" void kernel_launch(void* const* d_in, const int* in_sizes, int n_in,
                              void* d_out, int out_size)
{
    const float* X   = (const float*)d_in[0];
    const float* mv0 = (const float*)d_in[1];  const float* mg0 = (const float*)d_in[2];  const float* mb0 = (const float*)d_in[3];
    const float* mv1 = (const float*)d_in[4];  const float* mg1 = (const float*)d_in[5];  const float* mb1 = (const float*)d_in[6];
    const float* mv2 = (const float*)d_in[7];  const float* mg2 = (const float*)d_in[8];  const float* mb2 = (const float*)d_in[9];
    const float* sv0 = (const float*)d_in[10]; const float* sg0 = (const float*)d_in[11]; const float* sb0 = (const float*)d_in[12];
    const float* sv1 = (const float*)d_in[13]; const float* sg1 = (const float*)d_in[14]; const float* sb1 = (const float*)d_in[15];
    const float* sv2 = (const float*)d_in[16]; const float* sg2 = (const float*)d_in[17]; const float* sb2 = (const float*)d_in[18];
    const float* dv  = (const float*)d_in[19]; const float* dg  = (const float*)d_in[20]; const float* db  = (const float*)d_in[21];
    float* out = (float*)d_out;

    __half* hW1 = (__half*)sym(g_hW1);
    __half* hW2 = (__half*)sym(g_hW2);
    __half* gc0 = (__half*)sym(g_gc0);
    __half* gc1 = (__half*)sym(g_gc1);
    float*  M2  = (float*)sym(g_M2);
    float*  Z0  = (float*)sym(g_Z0);
    float*  Z1  = (float*)sym(g_Z1);
    __half* hHB = (__half*)sym(g_hHB);

    const int mod_smem = MOD_STAGES * 2 * BMM * SST * 4;     // 73728
    const int tc_smem  = TC_STAGES * 32768 + 2048 + 1024;    // 101376
    static int attr_done = 0;
    static cudaStream_t s2 = nullptr;
    static cudaEvent_t evF = nullptr, evR = nullptr, evM0 = nullptr,
                       evM2e = nullptr, evG1a = nullptr, evG2a = nullptr;
    if (!attr_done) {
        cudaFuncSetAttribute(gemm_mod_kernel, cudaFuncAttributeMaxDynamicSharedMemorySize, mod_smem);
        cudaFuncSetAttribute(tc_fp16_kernel<1>, cudaFuncAttributeMaxDynamicSharedMemorySize, tc_smem);
        cudaFuncSetAttribute(tc_fp16_kernel<2>, cudaFuncAttributeMaxDynamicSharedMemorySize, tc_smem);
        cudaStreamCreateWithFlags(&s2, cudaStreamNonBlocking);
        cudaEventCreateWithFlags(&evF,   cudaEventDisableTiming);
        cudaEventCreateWithFlags(&evR,   cudaEventDisableTiming);
        cudaEventCreateWithFlags(&evM0,  cudaEventDisableTiming);
        cudaEventCreateWithFlags(&evM2e, cudaEventDisableTiming);
        cudaEventCreateWithFlags(&evG1a, cudaEventDisableTiming);
        cudaEventCreateWithFlags(&evG2a, cudaEventDisableTiming);
        attr_done = 1;
    }

    // ---- capture fork ----
    cudaEventRecord(evF, 0);
    cudaStreamWaitEvent(s2, evF, 0);

    dim3 mgrid(512 / BNM, NS / BMM);        // (8, 16) = 128 CTAs

    // s2: Z prefix fill + siren prep, then mod1/mod2 (all off GEMM1's critical path)
    zfill_kernel<<<256, 256, 0, s2>>>(X);
    prep_rest_kernel<<<1124, 256, 0, s2>>>(sv1, sg1, sv2, sg2, dv, dg, sv0, sg0, sb0);
    cudaEventRecord(evR, s2);

    // stream 0: mod0 (only GEMM1 mod-dependency: gc0)
    gemm_mod_kernel<<<mgrid, 256, mod_smem>>>(X, mv0, mg0, mb0, nullptr, Z0, gc0, INCH);
    cudaEventRecord(evM0, 0);

    // s2: mod1 -> gc1 + Z1; mod2 -> M2  (concurrent with GEMM1)
    cudaStreamWaitEvent(s2, evM0, 0);
    gemm_mod_kernel<<<mgrid, 256, mod_smem, s2>>>(Z0, mv1, mg1, mb1, nullptr, Z1, gc1, KCAT);
    gemm_mod_kernel<<<mgrid, 256, mod_smem, s2>>>(Z1, mv2, mg2, mb2, M2, nullptr, nullptr, KCAT);
    cudaEventRecord(evM2e, s2);

    // big GEMMs, row-chunked for cross-kernel overlap
    cudaStreamWaitEvent(0, evR, 0);
    {
        const int HALF_BLKS = (ROWS / 128) / 2;     // 396
        dim3 gridH(4, HALF_BLKS);
        // GEMM1 halves on stream 0 (needs only gc0 + prep_rest)
        tc_fp16_kernel<1><<<gridH, 256, tc_smem>>>(nullptr, hW1, sb1, nullptr, gc0, hHB, 0);
        cudaEventRecord(evG1a, 0);
        tc_fp16_kernel<1><<<gridH, 256, tc_smem>>>(nullptr, hW1, sb1, nullptr, gc0, hHB, ROWS / 2);
        // GEMM2 first half on s2 (after mod2 in s2 order; waits G1a)
        cudaStreamWaitEvent(s2, evG1a, 0);
        tc_fp16_kernel<2><<<gridH, 256, tc_smem, s2>>>(hHB, hW2, sb2, M2, gc1, nullptr, 0);
        cudaEventRecord(evG2a, s2);
        // GEMM2 second half on stream 0 (needs mod1/mod2 results)
        cudaStreamWaitEvent(0, evM2e, 0);
        tc_fp16_kernel<2><<<gridH, 256, tc_smem>>>(hHB, hW2, sb2, M2, gc1, nullptr, ROWS / 2);
    }

    // cumsum joins both GEMM2 halves
    cudaStreamWaitEvent(0, evG2a, 0);
    cumsum_kernel<<<(NS * 32 + 255) / 256, 256>>>(out, db);
    (void)in_sizes; (void)n_in; (void)out_size;
}

// round 17
// speedup vs baseline: 1.1483x; 1.1483x over previous
#include <cuda_runtime.h>
#include <cuda_fp16.h>
#include <cstdint>

// ---------------- problem constants ----------------
#define NS      1024
#define NV      99
#define ROWS    (NS*NV)       // 101376
#define INCH    64
#define MH      512
#define SH      512
#define KCAT    (INCH+MH)     // 576
#define SCALE0  30.0f

// ---------------- device scratch ----------------
__device__ __half g_hW1[SH*SH];
__device__ __half g_hW2[SH*SH];
__device__ float  g_wdec[3*SH];
__device__ __half g_s0h[NV*SH];              // half(s0)
__device__ __half g_gc0[NS*MH];              // half(1 - M0)
__device__ __half g_gc1[NS*MH];              // half(1 - M1)
__device__ __half g_gc2[NS*MH];              // half(1 - M2)
__device__ float  g_Z0[NS*KCAT];
__device__ float  g_Z1[NS*KCAT];
__device__ __half g_hHB[(size_t)ROWS*SH];    // gated H1
__device__ float  g_dir8[(size_t)ROWS*24];   // 8 partials x 3 dims per row

__device__ __forceinline__ float rna_tf32(float x){
    float y; asm("cvt.rna.tf32.f32 %0, %1;" : "=f"(y) : "f"(x)); return y;
}
__device__ __forceinline__ void cp16(uint32_t s, const void* g){
    asm volatile("cp.async.cg.shared.global [%0], [%1], 16;" :: "r"(s), "l"(g));
}
__device__ __forceinline__ void ldsm4(uint32_t& r0, uint32_t& r1, uint32_t& r2, uint32_t& r3,
                                      uint32_t addr){
    asm volatile("ldmatrix.sync.aligned.m8n8.x4.shared.b16 {%0,%1,%2,%3}, [%4];"
                 : "=r"(r0), "=r"(r1), "=r"(r2), "=r"(r3) : "r"(addr));
}

// ---------------- shared rownorm body ----------------
__device__ __forceinline__ void rownorm_row(const float* __restrict__ v,
                                            const float* __restrict__ g,
                                            float* o32, __half* o16,
                                            int cols, int r, int mode, int tid,
                                            float* red)
{
    const float* vr = v + (size_t)r * cols;
    float ss = 0.f;
    for (int c = tid; c < cols; c += 256) { float x = vr[c]; ss += x * x; }
    red[tid] = ss; __syncthreads();
    for (int s = 128; s > 0; s >>= 1) {
        if (tid < s) red[tid] += red[tid + s];
        __syncthreads();
    }
    float scale = g[r] * rsqrtf(red[0]);
    for (int c = tid; c < cols; c += 256) {
        float w = vr[c] * scale;
        if (mode == 2)      o16[(size_t)r * cols + c] = __float2half(w);
        else                o32[(size_t)r * cols + c] = w;
    }
}

// ================= zfill: Z prefix = rna(X) =================
__global__ void zfill_kernel(const float* __restrict__ X)
{
    int i = blockIdx.x * 256 + threadIdx.x;    // 0..65535
    float v = rna_tf32(X[i]);
    int s = i >> 6, c = i & 63;
    g_Z0[(size_t)s * KCAT + c] = v;
    g_Z1[(size_t)s * KCAT + c] = v;
}

// ================= prep_rest: siren weight-norms + s0 table =====================
__global__ void prep_rest_kernel(const float* __restrict__ sv1, const float* __restrict__ sg1,
                                 const float* __restrict__ sv2, const float* __restrict__ sg2,
                                 const float* __restrict__ dv,  const float* __restrict__ dg,
                                 const float* __restrict__ sv0, const float* __restrict__ sg0,
                                 const float* __restrict__ sb0)
{
    __shared__ float red[256];
    int b = blockIdx.x, tid = threadIdx.x;
    if (b < 1025) {
        if      (b < 512)  rownorm_row(sv1, sg1, nullptr, g_hW1, SH, b,       2, tid, red);
        else if (b < 1024) rownorm_row(sv2, sg2, nullptr, g_hW2, SH, b - 512, 2, tid, red);
        else {
            for (int r = 0; r < 3; r++) rownorm_row(dv, dg, g_wdec, nullptr, SH, r, 0, tid, red);
        }
    } else {                            // s0 table (half): 99 blocks
        int p = b - 1025;
        float t = (float)p / 99.f;
        for (int j = tid; j < SH; j += 256) {
            float vv = sv0[j];
            float w  = sg0[j] * vv * rsqrtf(vv * vv);
            g_s0h[p * SH + j] = __float2half(sinf(SCALE0 * (t * w + sb0[j])));
        }
    }
}

// ================= mod GEMM: raw weights, fused weight-norm in epilogue ==========
// hcout = half(1 - silu(scale*acc+bias));  zout = rna(silu(...)) tail of Z
#define BMM 64
#define BNM 64
#define BKM 32
#define SST 36
#define MOD_STAGES 4
__global__ __launch_bounds__(256, 2)
void gemm_mod_kernel(const float* __restrict__ A, const float* __restrict__ V,
                     const float* __restrict__ gvec, const float* __restrict__ bias,
                     float* __restrict__ zout, __half* __restrict__ hcout, int K)
{
    extern __shared__ float sm[];
    float* sA = sm;
    float* sB = sm + MOD_STAGES * BMM * SST;
    const int tid = threadIdx.x;
    const int rowBase = blockIdx.y * BMM;
    const int colBase = blockIdx.x * BNM;
    const uint32_t sA_u = (uint32_t)__cvta_generic_to_shared(sA);
    const uint32_t sB_u = (uint32_t)__cvta_generic_to_shared(sB);
    const int lane = tid & 31, warp = tid >> 5;
    const int wm = warp & 3, wn = warp >> 2;         // warp tile 16 x 32
    const int gg = lane >> 2, tt = lane & 3;
    float acc[4][4] = {};
    float ss[4] = {0.f, 0.f, 0.f, 0.f};
    const int nk = K / BKM;

    auto load_stage = [&](int i, int buf){
        int k0 = i * BKM;
        #pragma unroll
        for (int it = 0; it < 2; it++){
            int c  = tid + it * 256;
            int r  = c >> 3;
            int kc = (c & 7) * 4;
            cp16(sA_u + (uint32_t)((buf * BMM * SST + r * SST + kc) * 4),
                 &A[(size_t)(rowBase + r) * K + k0 + kc]);
            cp16(sB_u + (uint32_t)((buf * BNM * SST + r * SST + kc) * 4),
                 &V[(size_t)(colBase + r) * K + k0 + kc]);
        }
        asm volatile("cp.async.commit_group;");
    };

    for (int s = 0; s < (nk < 3 ? nk : 3); s++) load_stage(s, s);

    for (int i = 0; i < nk; i++){
        if      (i + 3 <= nk) asm volatile("cp.async.wait_group 2;" ::: "memory");
        else if (i + 2 <= nk) asm volatile("cp.async.wait_group 1;" ::: "memory");
        else                  asm volatile("cp.async.wait_group 0;" ::: "memory");
        __syncthreads();
        const float* cA = sA + (i % MOD_STAGES) * BMM * SST;
        const float* cB = sB + (i % MOD_STAGES) * BNM * SST;
        #pragma unroll
        for (int kk = 0; kk < BKM; kk += 8){
            uint32_t a[4], b[4][2];
            {
                int r = wm * 16 + gg;
                a[0] = __float_as_uint(rna_tf32(cA[r * SST + kk + tt]));
                a[1] = __float_as_uint(rna_tf32(cA[(r + 8) * SST + kk + tt]));
                a[2] = __float_as_uint(rna_tf32(cA[r * SST + kk + tt + 4]));
                a[3] = __float_as_uint(rna_tf32(cA[(r + 8) * SST + kk + tt + 4]));
            }
            #pragma unroll
            for (int ni = 0; ni < 4; ni++){
                int c = wn * 32 + ni * 8 + gg;
                float bf0 = cB[c * SST + kk + tt];
                float bf1 = cB[c * SST + kk + tt + 4];
                ss[ni] = fmaf(bf0, bf0, ss[ni]);
                ss[ni] = fmaf(bf1, bf1, ss[ni]);
                b[ni][0] = __float_as_uint(rna_tf32(bf0));
                b[ni][1] = __float_as_uint(rna_tf32(bf1));
            }
            #pragma unroll
            for (int ni = 0; ni < 4; ni++){
                float* d = acc[ni];
                asm volatile(
                    "mma.sync.aligned.m16n8k8.row.col.f32.tf32.tf32.f32 "
                    "{%0,%1,%2,%3}, {%4,%5,%6,%7}, {%8,%9}, {%0,%1,%2,%3};"
                    : "+f"(d[0]), "+f"(d[1]), "+f"(d[2]), "+f"(d[3])
                    : "r"(a[0]), "r"(a[1]), "r"(a[2]), "r"(a[3]),
                      "r"(b[ni][0]), "r"(b[ni][1]));
            }
        }
        __syncthreads();
        if (i + 3 < nk) load_stage(i + 3, (i + 3) % MOD_STAGES);
    }

    // sumsq quad reduce: all 4 lanes of each quad hold the col (ni*8+gg) total
    #pragma unroll
    for (int ni = 0; ni < 4; ni++){
        ss[ni] += __shfl_xor_sync(0xFFFFFFFFu, ss[ni], 1);
        ss[ni] += __shfl_xor_sync(0xFFFFFFFFu, ss[ni], 2);
    }

    int row0 = rowBase + wm * 16 + gg;
    #pragma unroll
    for (int ni = 0; ni < 4; ni++){
        int col = colBase + wn * 32 + ni * 8 + tt * 2;
        float s0 = __shfl_sync(0xFFFFFFFFu, ss[ni], tt * 8);        // gg = 2tt quad
        float s1 = __shfl_sync(0xFFFFFFFFu, ss[ni], tt * 8 + 4);    // gg = 2tt+1 quad
        float sc0 = gvec[col]     * rsqrtf(s0);
        float sc1 = gvec[col + 1] * rsqrtf(s1);
        float b0 = bias[col], b1 = bias[col + 1];
        #pragma unroll
        for (int h = 0; h < 2; h++){
            int row = row0 + h * 8;
            float v0 = acc[ni][h * 2 + 0] * sc0 + b0;
            float v1 = acc[ni][h * 2 + 1] * sc1 + b1;
            v0 = v0 / (1.f + __expf(-v0));
            v1 = v1 / (1.f + __expf(-v1));
            if (hcout)
                *reinterpret_cast<__half2*>(&hcout[(size_t)row * 512 + col]) =
                    __floats2half2_rn(1.f - v0, 1.f - v1);
            if (zout)
                *reinterpret_cast<float2*>(&zout[(size_t)row * KCAT + 64 + col]) =
                    make_float2(rna_tf32(v0), rna_tf32(v1));
        }
    }
}

// ================= fp16 tensor-core GEMM (rows-chunked), 3-stage pipeline ========
// MODE 1: A = gc0(half)*s0h(half) produced on the fly; epilogue gates by gc1(half2)
//         and stores gated half H1.
// MODE 2: A = hHB loaded via cp.async; epilogue gates by gc2(half2), decoder
//         partials -> g_dir8 (per-warp slot, race-free).
#define BK2 64
#define TC_STAGES 3

template<int MODE>
__global__ __launch_bounds__(256, 2)
void tc_fp16_kernel(const __half* __restrict__ A, const __half* __restrict__ W,
                    const float* __restrict__ bias, const __half* __restrict__ gateE,
                    __half* __restrict__ out, int rowOff)
{
    extern __shared__ __align__(1024) char smem_raw[];
    uint32_t base  = (uint32_t)__cvta_generic_to_shared(smem_raw);
    uint32_t abase = (base + 1023u) & ~1023u;
    const int tid = threadIdx.x, warp = tid >> 5, lane = tid & 31;
    const int rowBase = rowOff + blockIdx.y * 128, colBase = blockIdx.x * 128;
    const int wm = warp & 3, wn = warp >> 2;
    const int gl = (lane >> 3) & 1, gh = lane >> 4, lr = lane & 7;

    float* wds = reinterpret_cast<float*>(smem_raw + (abase - base) + TC_STAGES * 32768);
    if (MODE == 2 && tid < 128) {
        #pragma unroll
        for (int d = 0; d < 3; d++)
            wds[d * 128 + tid] = g_wdec[d * 512 + colBase + tid];
    }

    auto load_B = [&](int t, int buf){
        uint32_t bBuf = abase + buf * 32768 + 16384;
        int k0 = t * BK2;
        #pragma unroll
        for (int it = 0; it < 4; it++){
            int idx = tid + it * 256;
            int r = idx >> 3, c = idx & 7;
            uint32_t off = (uint32_t)(r * 128 + ((c ^ (r & 7)) * 16));
            cp16(bBuf + off, &W[(size_t)(colBase + r) * 512 + k0 + c * 8]);
        }
    };
    auto load_A = [&](int t, int buf){
        uint32_t aBuf = abase + buf * 32768;
        int k0 = t * BK2;
        #pragma unroll
        for (int it = 0; it < 4; it++){
            int idx = tid + it * 256;
            int r = idx >> 3, c = idx & 7;
            uint32_t off = (uint32_t)(r * 128 + ((c ^ (r & 7)) * 16));
            cp16(aBuf + off, &A[(size_t)(rowBase + r) * 512 + k0 + c * 8]);
        }
    };
    auto produce_A = [&](int t, int buf){     // MODE 1: gc0 * s0h (all-half path)
        uint32_t aBuf = abase + buf * 32768;
        int k0 = t * BK2;
        #pragma unroll
        for (int it = 0; it < 4; it++){
            int idx = tid + it * 256;
            int r = idx >> 3, c = idx & 7;
            int row = rowBase + r;
            int strand = row / NV, p = row - strand * NV;
            uint4 mv = *reinterpret_cast<const uint4*>(&g_gc0[(size_t)strand * MH + k0 + c * 8]);
            uint4 sv = *reinterpret_cast<const uint4*>(&g_s0h[p * SH + k0 + c * 8]);
            __half2 h0 = __hmul2(*reinterpret_cast<__half2*>(&mv.x), *reinterpret_cast<__half2*>(&sv.x));
            __half2 h1 = __hmul2(*reinterpret_cast<__half2*>(&mv.y), *reinterpret_cast<__half2*>(&sv.y));
            __half2 h2 = __hmul2(*reinterpret_cast<__half2*>(&mv.z), *reinterpret_cast<__half2*>(&sv.z));
            __half2 h3 = __hmul2(*reinterpret_cast<__half2*>(&mv.w), *reinterpret_cast<__half2*>(&sv.w));
            uint32_t off = (uint32_t)(r * 128 + ((c ^ (r & 7)) * 16));
            asm volatile("st.shared.v4.b32 [%0], {%1,%2,%3,%4};"
                         :: "r"(aBuf + off),
                            "r"(*reinterpret_cast<uint32_t*>(&h0)),
                            "r"(*reinterpret_cast<uint32_t*>(&h1)),
                            "r"(*reinterpret_cast<uint32_t*>(&h2)),
                            "r"(*reinterpret_cast<uint32_t*>(&h3)) : "memory");
        }
    };
    auto load_stage = [&](int t, int buf){
        if (MODE == 1) produce_A(t, buf); else load_A(t, buf);
        load_B(t, buf);
        asm volatile("cp.async.commit_group;");
    };

    float acc[2][8][4] = {};

    load_stage(0, 0);
    load_stage(1, 1);
    load_stage(2, 2);

    for (int t = 0; t < 8; t++){
        if (t < 7) asm volatile("cp.async.wait_group 2;" ::: "memory");
        else       asm volatile("cp.async.wait_group 0;" ::: "memory");
        __syncthreads();
        int buf = t % TC_STAGES;
        uint32_t aBuf = abase + buf * 32768;
        uint32_t bBuf = aBuf + 16384;

        #pragma unroll
        for (int kk = 0; kk < 4; kk++){
            int kc = kk * 2 + gh;
            uint32_t a[2][4], b[4][4];
            #pragma unroll
            for (int mi = 0; mi < 2; mi++){
                int row = wm * 32 + mi * 16 + gl * 8 + lr;
                ldsm4(a[mi][0], a[mi][1], a[mi][2], a[mi][3],
                      aBuf + (uint32_t)(row * 128 + ((kc ^ lr) * 16)));
            }
            #pragma unroll
            for (int nq = 0; nq < 4; nq++){
                int nrow = wn * 64 + nq * 16 + gl * 8 + lr;
                ldsm4(b[nq][0], b[nq][1], b[nq][2], b[nq][3],
                      bBuf + (uint32_t)(nrow * 128 + ((kc ^ lr) * 16)));
            }
            #pragma unroll
            for (int mi = 0; mi < 2; mi++)
                #pragma unroll
                for (int nq = 0; nq < 4; nq++){
                    #pragma unroll
                    for (int hf = 0; hf < 2; hf++){
                        float* d = acc[mi][nq * 2 + hf];
                        asm volatile(
                            "mma.sync.aligned.m16n8k16.row.col.f32.f16.f16.f32 "
                            "{%0,%1,%2,%3}, {%4,%5,%6,%7}, {%8,%9}, {%0,%1,%2,%3};"
                            : "+f"(d[0]), "+f"(d[1]), "+f"(d[2]), "+f"(d[3])
                            : "r"(a[mi][0]), "r"(a[mi][1]), "r"(a[mi][2]), "r"(a[mi][3]),
                              "r"(b[nq][hf]), "r"(b[nq][2 + hf]));
                    }
                }
        }
        __syncthreads();
        if (t + 3 < 8) load_stage(t + 3, (t + 3) % TC_STAGES);
    }

    // ---- epilogue ----
    const int gg = lane >> 2, tt = lane & 3;
    float p3[4][3];
    if (MODE == 2){
        #pragma unroll
        for (int q = 0; q < 4; q++){ p3[q][0] = 0.f; p3[q][1] = 0.f; p3[q][2] = 0.f; }
    }
    #pragma unroll
    for (int mi = 0; mi < 2; mi++){
        int row0 = rowBase + wm * 32 + mi * 16 + gg;
        #pragma unroll
        for (int ni = 0; ni < 8; ni++){
            int col = colBase + wn * 64 + ni * 8 + tt * 2;
            float b0 = bias[col], b1 = bias[col + 1];
            #pragma unroll
            for (int h = 0; h < 2; h++){
                int row = row0 + h * 8;
                int strand = row / NV;
                float2 gv = __half22float2(
                    *reinterpret_cast<const __half2*>(&gateE[(size_t)strand * MH + col]));
                float v0 = gv.x * __sinf(acc[mi][ni][h * 2 + 0] + b0);
                float v1 = gv.y * __sinf(acc[mi][ni][h * 2 + 1] + b1);
                if (MODE == 1){
                    *reinterpret_cast<__half2*>(&out[(size_t)row * 512 + col]) =
                        __floats2half2_rn(v0, v1);
                } else {
                    int lc = col - colBase;
                    int q = mi * 2 + h;
                    #pragma unroll
                    for (int d = 0; d < 3; d++)
                        p3[q][d] += v0 * wds[d * 128 + lc] + v1 * wds[d * 128 + lc + 1];
                }
            }
        }
    }
    if (MODE == 2){
        #pragma unroll
        for (int q = 0; q < 4; q++)
            #pragma unroll
            for (int d = 0; d < 3; d++){
                float v = p3[q][d];
                v += __shfl_xor_sync(0xFFFFFFFFu, v, 1);
                v += __shfl_xor_sync(0xFFFFFFFFu, v, 2);
                p3[q][d] = v;
            }
        if (tt == 0){
            int slot = blockIdx.x * 2 + wn;     // 8 race-free slots per row
            int rb = rowBase + wm * 32 + gg;
            #pragma unroll
            for (int q = 0; q < 4; q++){
                int row = rb + (q & 1) * 8 + (q >> 1) * 16;
                #pragma unroll
                for (int d = 0; d < 3; d++)
                    g_dir8[(size_t)row * 24 + slot * 3 + d] = p3[q][d] * 0.01f;
            }
        }
    }
}

// ================= cumsum: warp per strand, shfl inclusive scan =================
__global__ void cumsum_kernel(float* __restrict__ out, const float* __restrict__ bd)
{
    int gw = (blockIdx.x * blockDim.x + threadIdx.x) >> 5;   // strand
    int lane = threadIdx.x & 31;
    if (gw >= NS) return;
    int s = gw;
    float bias0 = bd[0] * 0.01f, bias1 = bd[1] * 0.01f, bias2 = bd[2] * 0.01f;
    if (lane < 3) out[(size_t)s * 300 + lane] = 0.f;
    float c0 = 0.f, c1 = 0.f, c2 = 0.f;
    #pragma unroll
    for (int ch = 0; ch < 4; ch++){
        int p = ch * 32 + lane;
        float v0 = 0.f, v1 = 0.f, v2 = 0.f;
        if (p < NV){
            const float* b = &g_dir8[(size_t)(s * NV + p) * 24];
            #pragma unroll
            for (int j = 0; j < 8; j++){
                v0 += b[j * 3 + 0];
                v1 += b[j * 3 + 1];
                v2 += b[j * 3 + 2];
            }
            v0 += bias0; v1 += bias1; v2 += bias2;
        }
        #pragma unroll
        for (int o = 1; o < 32; o <<= 1){
            float t0 = __shfl_up_sync(0xFFFFFFFFu, v0, o);
            float t1 = __shfl_up_sync(0xFFFFFFFFu, v1, o);
            float t2 = __shfl_up_sync(0xFFFFFFFFu, v2, o);
            if (lane >= o){ v0 += t0; v1 += t1; v2 += t2; }
        }
        v0 += c0; v1 += c1; v2 += c2;
        if (p < NV){
            float* ob = out + (size_t)s * 300 + (size_t)(p + 1) * 3;
            ob[0] = v0; ob[1] = v1; ob[2] = v2;
        }
        c0 = __shfl_sync(0xFFFFFFFFu, v0, 31);
        c1 = __shfl_sync(0xFFFFFFFFu, v1, 31);
        c2 = __shfl_sync(0xFFFFFFFFu, v2, 31);
    }
}

// ================= host launch =================
static void* sym(const void* s) { void* p = nullptr; cudaGetSymbolAddress(&p, s); return p; }

extern "C" void kernel_launch(void* const* d_in, const int* in_sizes, int n_in,
                              void* d_out, int out_size)
{
    const float* X   = (const float*)d_in[0];
    const float* mv0 = (const float*)d_in[1];  const float* mg0 = (const float*)d_in[2];  const float* mb0 = (const float*)d_in[3];
    const float* mv1 = (const float*)d_in[4];  const float* mg1 = (const float*)d_in[5];  const float* mb1 = (const float*)d_in[6];
    const float* mv2 = (const float*)d_in[7];  const float* mg2 = (const float*)d_in[8];  const float* mb2 = (const float*)d_in[9];
    const float* sv0 = (const float*)d_in[10]; const float* sg0 = (const float*)d_in[11]; const float* sb0 = (const float*)d_in[12];
    const float* sv1 = (const float*)d_in[13]; const float* sg1 = (const float*)d_in[14]; const float* sb1 = (const float*)d_in[15];
    const float* sv2 = (const float*)d_in[16]; const float* sg2 = (const float*)d_in[17]; const float* sb2 = (const float*)d_in[18];
    const float* dv  = (const float*)d_in[19]; const float* dg  = (const float*)d_in[20]; const float* db  = (const float*)d_in[21];
    float* out = (float*)d_out;

    __half* hW1 = (__half*)sym(g_hW1);
    __half* hW2 = (__half*)sym(g_hW2);
    __half* gc0 = (__half*)sym(g_gc0);
    __half* gc1 = (__half*)sym(g_gc1);
    __half* gc2 = (__half*)sym(g_gc2);
    float*  Z0  = (float*)sym(g_Z0);
    float*  Z1  = (float*)sym(g_Z1);
    __half* hHB = (__half*)sym(g_hHB);

    const int mod_smem = MOD_STAGES * 2 * BMM * SST * 4;     // 73728
    const int tc_smem  = TC_STAGES * 32768 + 2048 + 1024;    // 101376
    static int attr_done = 0;
    static cudaStream_t s2 = nullptr;
    static cudaEvent_t evF = nullptr, evZ = nullptr, evR = nullptr,
                       evM1 = nullptr, evM2 = nullptr, evG1a = nullptr, evG2a = nullptr;
    if (!attr_done) {
        cudaFuncSetAttribute(gemm_mod_kernel, cudaFuncAttributeMaxDynamicSharedMemorySize, mod_smem);
        cudaFuncSetAttribute(tc_fp16_kernel<1>, cudaFuncAttributeMaxDynamicSharedMemorySize, tc_smem);
        cudaFuncSetAttribute(tc_fp16_kernel<2>, cudaFuncAttributeMaxDynamicSharedMemorySize, tc_smem);
        cudaStreamCreateWithFlags(&s2, cudaStreamNonBlocking);
        cudaEventCreateWithFlags(&evF,   cudaEventDisableTiming);
        cudaEventCreateWithFlags(&evZ,   cudaEventDisableTiming);
        cudaEventCreateWithFlags(&evR,   cudaEventDisableTiming);
        cudaEventCreateWithFlags(&evM1,  cudaEventDisableTiming);
        cudaEventCreateWithFlags(&evM2,  cudaEventDisableTiming);
        cudaEventCreateWithFlags(&evG1a, cudaEventDisableTiming);
        cudaEventCreateWithFlags(&evG2a, cudaEventDisableTiming);
        attr_done = 1;
    }

    // ---- capture fork ----
    cudaEventRecord(evF, 0);
    cudaStreamWaitEvent(s2, evF, 0);

    dim3 mgrid(512 / BNM, NS / BMM);        // (8, 16) = 128 CTAs

    // s2: Z prefix fill + siren prep (off critical path)
    zfill_kernel<<<256, 256, 0, s2>>>(X);
    cudaEventRecord(evZ, s2);
    prep_rest_kernel<<<1124, 256, 0, s2>>>(sv1, sg1, sv2, sg2, dv, dg, sv0, sg0, sb0);
    cudaEventRecord(evR, s2);

    // stream 0: mod chain (R15 structure)
    gemm_mod_kernel<<<mgrid, 256, mod_smem>>>(X, mv0, mg0, mb0, Z0, gc0, INCH);
    cudaStreamWaitEvent(0, evZ, 0);
    gemm_mod_kernel<<<mgrid, 256, mod_smem>>>(Z0, mv1, mg1, mb1, Z1, gc1, KCAT);
    cudaEventRecord(evM1, 0);
    // mod2 on s2 (after prep_rest there; waits mod1) -> gc2
    cudaStreamWaitEvent(s2, evM1, 0);
    gemm_mod_kernel<<<mgrid, 256, mod_smem, s2>>>(Z1, mv2, mg2, mb2, nullptr, gc2, KCAT);
    cudaEventRecord(evM2, s2);

    // big GEMMs, row-chunked for cross-kernel overlap
    cudaStreamWaitEvent(0, evR, 0);
    {
        const int HALF_BLKS = (ROWS / 128) / 2;     // 396
        dim3 gridH(4, HALF_BLKS);
        // GEMM1 halves on stream 0 (needs gc0 + gc1 + prep_rest)
        tc_fp16_kernel<1><<<gridH, 256, tc_smem>>>(nullptr, hW1, sb1, gc1, hHB, 0);
        cudaEventRecord(evG1a, 0);
        tc_fp16_kernel<1><<<gridH, 256, tc_smem>>>(nullptr, hW1, sb1, gc1, hHB, ROWS / 2);
        // GEMM2 first half on s2 (after mod2 there; waits G1a)
        cudaStreamWaitEvent(s2, evG1a, 0);
        tc_fp16_kernel<2><<<gridH, 256, tc_smem, s2>>>(hHB, hW2, sb2, gc2, nullptr, 0);
        cudaEventRecord(evG2a, s2);
        // GEMM2 second half on stream 0 (needs mod2 result)
        cudaStreamWaitEvent(0, evM2, 0);
        tc_fp16_kernel<2><<<gridH, 256, tc_smem>>>(hHB, hW2, sb2, gc2, nullptr, ROWS / 2);
    }

    // cumsum joins both GEMM2 halves
    cudaStreamWaitEvent(0, evG2a, 0);
    cumsum_kernel<<<(NS * 32 + 255) / 256, 256>>>(out, db);
    (void)in_sizes; (void)n_in; (void)out_size;
}